// round 8
// baseline (speedup 1.0000x reference)
#include <cuda_runtime.h>
#include <cstdint>

#define NB 8192
#define NP 8192
#define NF 256
#define BM 128
#define BN 128
#define BK 32
#define NTM (NB / BM)       // 64
#define NTN (NP / BN)       // 32
#define NTILES (NTM * NTN)  // 2048... (64*32)=2048? no: 64*32=2048
#define STAGES 3
#define AKB 16384           // 128x32 fp32 block bytes (A or B)
#define STAGE_B (2 * AKB)   // 32 KB
#define SMEM_BYTES (STAGES * STAGE_B)  // 96 KB

// ---------------- device scratch (allocation-free) ----------------
__device__ float g_xsq[NB];
__device__ float g_psq[NP];
// fragment-order permuted tf32 copies: [tile][kb(8)][16KB block]
__device__ __align__(1024) float g_Xr[(size_t)NB * NF];
__device__ __align__(1024) float g_Pr[(size_t)NP * NF];

__device__ __forceinline__ uint32_t smem_u32(const void* p) {
    uint32_t a;
    asm("{ .reg .u64 t; cvta.to.shared.u64 t, %1; cvt.u32.u64 %0, t; }" : "=r"(a) : "l"(p));
    return a;
}

// ---------------- prepass: tf32 round + permute + row norms (same as R6) ----------------
// A block (128 m x 32 k): atom = 16 m x 8 k = 512B, idx = ak*8 + am
// B block (128 n x 32 k): atom = 16 n x 8 k = 512B (two n8 subtiles), idx = ak*8 + pn
__global__ __launch_bounds__(256) void prep_kernel(const float* __restrict__ X,
                                                   const float* __restrict__ P) {
    int row = blockIdx.x;
    bool isP = row >= NB;
    int r = isP ? row - NB : row;
    int t = threadIdx.x;

    float v = (isP ? P : X)[(size_t)r * NF + t];
    uint32_t u;
    asm("cvt.rna.tf32.f32 %0, %1;" : "=r"(u) : "f"(v));

    int tile = r >> 7, rin = r & 127, kb = t >> 5, kin = t & 31;
    int ak = kin >> 3, cc = kin & 7;
    char* base = (char*)(isP ? g_Pr : g_Xr) + (((size_t)tile * 8 + kb) << 14);
    uint32_t off;
    if (!isP) {
        int am = rin >> 4, rr = rin & 15;
        off = ((uint32_t)(ak * 8 + am) << 9)
            + (uint32_t)((rr & 7) * 4 + (cc & 3)) * 16u
            + ((uint32_t)((rr >> 3) | ((cc >> 2) << 1)) << 2);
    } else {
        int pn = rin >> 4, sub = (rin >> 3) & 1, nn = rin & 7;
        off = ((uint32_t)(ak * 8 + pn) << 9)
            + (uint32_t)(nn * 4 + (cc & 3)) * 16u
            + (uint32_t)(sub * 8)
            + ((uint32_t)(cc >> 2) << 2);
    }
    *reinterpret_cast<float*>(base + off) = __uint_as_float(u);

    float s = v * v;
    #pragma unroll
    for (int o = 16; o > 0; o >>= 1) s += __shfl_xor_sync(0xffffffffu, s, o);
    __shared__ float red[8];
    if ((t & 31) == 0) red[t >> 5] = s;
    __syncthreads();
    if (t == 0) {
        float tot = 0.f;
        #pragma unroll
        for (int i = 0; i < 8; i++) tot += red[i];
        (isP ? g_psq : g_xsq)[r] = tot;
    }
}

// ---------------- persistent main kernel ----------------
__global__ __launch_bounds__(256, 2) void gauss_mma_kernel(float* __restrict__ out) {
    extern __shared__ char sm[];
    const uint32_t sb = smem_u32(sm);

    const int tid = threadIdx.x;
    const int w = tid >> 5, lane = tid & 31;
    const int wm = w & 1, wn = w >> 1;      // 2(M) x 4(N); warp tile 64x32
    const int g = lane >> 2, tg = lane & 3;
    const int bid = blockIdx.x, stride = gridDim.x;

    const int totalTiles = NTM * NTN;                 // 2048
    const int myN = (bid < totalTiles) ? ((totalTiles - 1 - bid) / stride + 1) : 0;
    const int total = myN * 8;                        // global kt count for this CTA
    if (total == 0) return;

    // virtual tile index -> (tm, tn) with L2-friendly grouping (16 tn per supercol)
    auto tile_mn = [&](int v, int& tm, int& tn) {
        tn = ((v >> 10) << 4) | (v & 15);
        tm = (v & 1023) >> 4;
    };

    auto issue = [&](int gk, int st) {
        int v = bid + (gk >> 3) * stride;
        int kk = gk & 7;
        int tm, tn;
        tile_mn(v, tm, tn);
        const char* a = (const char*)g_Xr + (((size_t)tm * 8 + kk) << 14) + tid * 64;
        const char* b = (const char*)g_Pr + (((size_t)tn * 8 + kk) << 14) + tid * 64;
        const uint32_t so = sb + (uint32_t)st * STAGE_B + (uint32_t)tid * 64;
        #pragma unroll
        for (int j = 0; j < 4; j++) {
            asm volatile("cp.async.cg.shared.global [%0], [%1], 16;" :: "r"(so + j * 16), "l"(a + j * 16));
            asm volatile("cp.async.cg.shared.global [%0], [%1], 16;" :: "r"(so + AKB + j * 16), "l"(b + j * 16));
        }
        asm volatile("cp.async.commit_group;" ::: "memory");
    };

    float acc[4][4][4];
    #pragma unroll
    for (int mt = 0; mt < 4; mt++)
        #pragma unroll
        for (int nt = 0; nt < 4; nt++)
            #pragma unroll
            for (int q = 0; q < 4; q++) acc[mt][nt][q] = 0.f;

    const uint32_t laneOff = (uint32_t)lane * 16;
    uint32_t af[2][4][4];   // [buf][mt][a0..a3]
    uint32_t bf[2][2][4];   // [buf][pair][b0_lo, b1_lo, b0_hi, b1_hi]

    auto ldfrags = [&](int buf, uint32_t so, int ak) {
        #pragma unroll
        for (int mt = 0; mt < 4; mt++) {
            uint32_t addr = so + ((uint32_t)(ak * 8 + wm * 4 + mt) << 9) + laneOff;
            asm volatile("ld.shared.v4.b32 {%0,%1,%2,%3}, [%4];"
                         : "=r"(af[buf][mt][0]), "=r"(af[buf][mt][1]),
                           "=r"(af[buf][mt][2]), "=r"(af[buf][mt][3]) : "r"(addr));
        }
        #pragma unroll
        for (int pp = 0; pp < 2; pp++) {
            uint32_t addr = so + AKB + ((uint32_t)(ak * 8 + wn * 2 + pp) << 9) + laneOff;
            asm volatile("ld.shared.v4.b32 {%0,%1,%2,%3}, [%4];"
                         : "=r"(bf[buf][pp][0]), "=r"(bf[buf][pp][1]),
                           "=r"(bf[buf][pp][2]), "=r"(bf[buf][pp][3]) : "r"(addr));
        }
    };

    // prologue
    issue(0, 0);
    if (total > 1) issue(1, 1);
    asm volatile("cp.async.wait_group 1;" ::: "memory");
    __syncthreads();
    ldfrags(0, sb, 0);

    int sg = 0;   // stage of current gkt
    #pragma unroll 1
    for (int gkt = 0; gkt < total; gkt++) {
        const uint32_t so = sb + (uint32_t)sg * STAGE_B;
        const int sgn = (sg + 1 == STAGES) ? 0 : sg + 1;
        const int sg2 = (sgn + 1 == STAGES) ? 0 : sgn + 1;

        #pragma unroll
        for (int ak = 0; ak < 4; ak++) {
            if (ak == 0) {
                if (gkt + 2 < total) issue(gkt + 2, sg2);
            }
            if (ak < 3) {
                ldfrags((ak + 1) & 1, so, ak + 1);
            } else if (gkt + 1 < total) {
                // stage boundary before the last MMA block of this gkt
                if (gkt + 2 < total) {
                    asm volatile("cp.async.wait_group 1;" ::: "memory");
                } else {
                    asm volatile("cp.async.wait_group 0;" ::: "memory");
                }
                __syncthreads();
                ldfrags(0, sb + (uint32_t)sgn * STAGE_B, 0);
            }
            const int cur = ak & 1;
            #pragma unroll
            for (int mt = 0; mt < 4; mt++)
                #pragma unroll
                for (int nt = 0; nt < 4; nt++) {
                    const int pp = nt >> 1, ss = (nt & 1) * 2;
                    asm volatile(
                        "mma.sync.aligned.m16n8k8.row.col.f32.tf32.tf32.f32 "
                        "{%0,%1,%2,%3}, {%4,%5,%6,%7}, {%8,%9}, {%0,%1,%2,%3};"
                        : "+f"(acc[mt][nt][0]), "+f"(acc[mt][nt][1]),
                          "+f"(acc[mt][nt][2]), "+f"(acc[mt][nt][3])
                        : "r"(af[cur][mt][0]), "r"(af[cur][mt][1]),
                          "r"(af[cur][mt][2]), "r"(af[cur][mt][3]),
                          "r"(bf[cur][pp][ss]), "r"(bf[cur][pp][ss + 1]));
                }
        }

        if ((gkt & 7) == 7) {
            // ---------------- fused epilogue for finished tile ----------------
            int v = bid + (gkt >> 3) * stride;
            int tm, tn;
            tile_mn(v, tm, tn);
            const int orow0 = tm * BM + wm * 64 + g;
            const int ocol0 = tn * BN + wn * 32 + 2 * tg;

            #pragma unroll
            for (int mt = 0; mt < 4; mt++) {
                const int r0 = orow0 + mt * 16;
                const float xs0 = g_xsq[r0];
                const float xs1 = g_xsq[r0 + 8];
                float* orow_a = out + (size_t)r0 * NP;
                float* orow_b = out + (size_t)(r0 + 8) * NP;
                #pragma unroll
                for (int nt = 0; nt < 4; nt++) {
                    const int c = ocol0 + nt * 8;
                    const float p0 = g_psq[c];
                    const float p1 = g_psq[c + 1];
                    float d00 = fmaxf(fmaf(-2.f, acc[mt][nt][0], xs0 + p0), 1e-30f);
                    float d01 = fmaxf(fmaf(-2.f, acc[mt][nt][1], xs0 + p1), 1e-30f);
                    float d10 = fmaxf(fmaf(-2.f, acc[mt][nt][2], xs1 + p0), 1e-30f);
                    float d11 = fmaxf(fmaf(-2.f, acc[mt][nt][3], xs1 + p1), 1e-30f);
                    float2 v0 = make_float2(__expf(-0.5f * d00 * rsqrtf(d00)),
                                            __expf(-0.5f * d01 * rsqrtf(d01)));
                    float2 v1 = make_float2(__expf(-0.5f * d10 * rsqrtf(d10)),
                                            __expf(-0.5f * d11 * rsqrtf(d11)));
                    *reinterpret_cast<float2*>(orow_a + c) = v0;
                    *reinterpret_cast<float2*>(orow_b + c) = v1;
                }
            }
            #pragma unroll
            for (int mt = 0; mt < 4; mt++)
                #pragma unroll
                for (int nt = 0; nt < 4; nt++)
                    #pragma unroll
                    for (int q = 0; q < 4; q++) acc[mt][nt][q] = 0.f;
        }
        sg = sgn;
    }
}

// ---------------- launch ----------------
extern "C" void kernel_launch(void* const* d_in, const int* in_sizes, int n_in,
                              void* d_out, int out_size) {
    const float* x = (const float*)d_in[0];   // [8192, 256]
    const float* p = (const float*)d_in[1];   // [8192, 256]
    float* out = (float*)d_out;               // [8192, 8192]

    static int nsm = 0;
    if (nsm == 0) {
        cudaDeviceGetAttribute(&nsm, cudaDevAttrMultiProcessorCount, 0);
        if (nsm <= 0) nsm = 148;
        cudaFuncSetAttribute(gauss_mma_kernel,
                             cudaFuncAttributeMaxDynamicSharedMemorySize, SMEM_BYTES);
    }

    prep_kernel<<<NB + NP, 256>>>(x, p);

    gauss_mma_kernel<<<2 * nsm, 256, SMEM_BYTES>>>(out);
}

// round 9
// speedup vs baseline: 2.1633x; 2.1633x over previous
#include <cuda_runtime.h>
#include <cstdint>

#define NB 8192
#define NP 8192
#define NF 256
#define BM 128
#define BN 128
#define STAGES 3
#define AKB 16384           // 128x32 fp32 block bytes (A or B)
#define STAGE_B (2 * AKB)   // 32 KB
#define SMEM_BYTES (STAGES * STAGE_B)  // 96 KB
#define GKT 16              // 2 tiles x 8 k-steps, one fused stream

// ---------------- device scratch (allocation-free) ----------------
__device__ float g_xsq[NB];
__device__ float g_psq[NP];
// fragment-order permuted tf32 copies: [tile(64)][kb(8)][16KB block]
__device__ __align__(1024) float g_Xr[(size_t)NB * NF];
__device__ __align__(1024) float g_Pr[(size_t)NP * NF];

__device__ __forceinline__ uint32_t smem_u32(const void* p) {
    uint32_t a;
    asm("{ .reg .u64 t; cvta.to.shared.u64 t, %1; cvt.u32.u64 %0, t; }" : "=r"(a) : "l"(p));
    return a;
}

// ---------------- prepass: tf32 round + permute + row norms (same as R6) ----------------
// A block (128 m x 32 k): atom = 16 m x 8 k = 512B, idx = ak*8 + am
// B block (128 n x 32 k): atom = 16 n x 8 k = 512B (two n8 subtiles), idx = ak*8 + pn
__global__ __launch_bounds__(256) void prep_kernel(const float* __restrict__ X,
                                                   const float* __restrict__ P) {
    int row = blockIdx.x;
    bool isP = row >= NB;
    int r = isP ? row - NB : row;
    int t = threadIdx.x;

    float v = (isP ? P : X)[(size_t)r * NF + t];
    uint32_t u;
    asm("cvt.rna.tf32.f32 %0, %1;" : "=r"(u) : "f"(v));

    int tile = r >> 7, rin = r & 127, kb = t >> 5, kin = t & 31;
    int ak = kin >> 3, cc = kin & 7;
    char* base = (char*)(isP ? g_Pr : g_Xr) + (((size_t)tile * 8 + kb) << 14);
    uint32_t off;
    if (!isP) {
        int am = rin >> 4, rr = rin & 15;
        off = ((uint32_t)(ak * 8 + am) << 9)
            + (uint32_t)((rr & 7) * 4 + (cc & 3)) * 16u
            + ((uint32_t)((rr >> 3) | ((cc >> 2) << 1)) << 2);
    } else {
        int pn = rin >> 4, sub = (rin >> 3) & 1, nn = rin & 7;
        off = ((uint32_t)(ak * 8 + pn) << 9)
            + (uint32_t)(nn * 4 + (cc & 3)) * 16u
            + (uint32_t)(sub * 8)
            + ((uint32_t)(cc >> 2) << 2);
    }
    *reinterpret_cast<float*>(base + off) = __uint_as_float(u);

    float s = v * v;
    #pragma unroll
    for (int o = 16; o > 0; o >>= 1) s += __shfl_xor_sync(0xffffffffu, s, o);
    __shared__ float red[8];
    if ((t & 31) == 0) red[t >> 5] = s;
    __syncthreads();
    if (t == 0) {
        float tot = 0.f;
        #pragma unroll
        for (int i = 0; i < 8; i++) tot += red[i];
        (isP ? g_psq : g_xsq)[r] = tot;
    }
}

// ---------------- main kernel: 2 fused 128x128 tiles per CTA ----------------
__global__ __launch_bounds__(256, 2) void gauss_mma_kernel(float* __restrict__ out) {
    extern __shared__ char sm[];
    const uint32_t sb = smem_u32(sm);

    // pair mapping: ids 2c, 2c+1 share tm (same A stream), tn1 = tn0 + 1
    const int id0 = blockIdx.x * 2;
    const int tn0 = ((id0 >> 10) << 4) | (id0 & 15);
    const int tm  = (id0 & 1023) >> 4;
    const int tn1 = tn0 + 1;   // id0 even -> (id0&15) even -> no wrap

    const int tid = threadIdx.x;
    const int w = tid >> 5, lane = tid & 31;
    const int wm = w & 1, wn = w >> 1;      // 2(M) x 4(N); warp tile 64x32
    const int g = lane >> 2, tg = lane & 3;

    const char* gA  = (const char*)g_Xr + ((size_t)tm  * 8 << 14);
    const char* gB0 = (const char*)g_Pr + ((size_t)tn0 * 8 << 14);
    const char* gB1 = (const char*)g_Pr + ((size_t)tn1 * 8 << 14);

    auto issue = [&](int gk) {   // gk compile-time under full unroll
        const char* a = gA + ((size_t)(gk & 7) << 14) + tid * 64;
        const char* b = ((gk < 8) ? gB0 : gB1) + ((size_t)(gk & 7) << 14) + tid * 64;
        const uint32_t so = sb + (uint32_t)(gk % 3) * STAGE_B + (uint32_t)tid * 64;
        #pragma unroll
        for (int j = 0; j < 4; j++) {
            asm volatile("cp.async.cg.shared.global [%0], [%1], 16;" :: "r"(so + j * 16), "l"(a + j * 16));
            asm volatile("cp.async.cg.shared.global [%0], [%1], 16;" :: "r"(so + AKB + j * 16), "l"(b + j * 16));
        }
        asm volatile("cp.async.commit_group;" ::: "memory");
    };

    float acc[4][4][4];
    #pragma unroll
    for (int mt = 0; mt < 4; mt++)
        #pragma unroll
        for (int nt = 0; nt < 4; nt++)
            #pragma unroll
            for (int q = 0; q < 4; q++) acc[mt][nt][q] = 0.f;

    const uint32_t laneOff = (uint32_t)lane * 16;
    uint32_t af[2][4][4];   // [buf][mt][a0..a3]
    uint32_t bf[2][2][4];   // [buf][pair][b0_lo, b1_lo, b0_hi, b1_hi]

    auto ldfrags = [&](int buf, uint32_t so, int ak) {
        #pragma unroll
        for (int mt = 0; mt < 4; mt++) {
            uint32_t addr = so + ((uint32_t)(ak * 8 + wm * 4 + mt) << 9) + laneOff;
            asm volatile("ld.shared.v4.b32 {%0,%1,%2,%3}, [%4];"
                         : "=r"(af[buf][mt][0]), "=r"(af[buf][mt][1]),
                           "=r"(af[buf][mt][2]), "=r"(af[buf][mt][3]) : "r"(addr));
        }
        #pragma unroll
        for (int pp = 0; pp < 2; pp++) {
            uint32_t addr = so + AKB + ((uint32_t)(ak * 8 + wn * 2 + pp) << 9) + laneOff;
            asm volatile("ld.shared.v4.b32 {%0,%1,%2,%3}, [%4];"
                         : "=r"(bf[buf][pp][0]), "=r"(bf[buf][pp][1]),
                           "=r"(bf[buf][pp][2]), "=r"(bf[buf][pp][3]) : "r"(addr));
        }
    };

    auto epilogue = [&](int tn) {
        const int orow0 = tm * BM + wm * 64 + g;
        const int ocol0 = tn * BN + wn * 32 + 2 * tg;
        #pragma unroll
        for (int mt = 0; mt < 4; mt++) {
            const int r0 = orow0 + mt * 16;
            const float xs0 = g_xsq[r0];
            const float xs1 = g_xsq[r0 + 8];
            float* orow_a = out + (size_t)r0 * NP;
            float* orow_b = out + (size_t)(r0 + 8) * NP;
            #pragma unroll
            for (int nt = 0; nt < 4; nt++) {
                const int cc = ocol0 + nt * 8;
                const float p0 = g_psq[cc];
                const float p1 = g_psq[cc + 1];
                float d00 = fmaxf(fmaf(-2.f, acc[mt][nt][0], xs0 + p0), 1e-30f);
                float d01 = fmaxf(fmaf(-2.f, acc[mt][nt][1], xs0 + p1), 1e-30f);
                float d10 = fmaxf(fmaf(-2.f, acc[mt][nt][2], xs1 + p0), 1e-30f);
                float d11 = fmaxf(fmaf(-2.f, acc[mt][nt][3], xs1 + p1), 1e-30f);
                float2 v0 = make_float2(__expf(-0.5f * d00 * rsqrtf(d00)),
                                        __expf(-0.5f * d01 * rsqrtf(d01)));
                float2 v1 = make_float2(__expf(-0.5f * d10 * rsqrtf(d10)),
                                        __expf(-0.5f * d11 * rsqrtf(d11)));
                *reinterpret_cast<float2*>(orow_a + cc) = v0;
                *reinterpret_cast<float2*>(orow_b + cc) = v1;
            }
        }
    };

    // prologue (once per CTA, covers both tiles)
    issue(0);
    issue(1);
    asm volatile("cp.async.wait_group 1;" ::: "memory");
    __syncthreads();
    ldfrags(0, sb, 0);

    #pragma unroll
    for (int gkt = 0; gkt < GKT; gkt++) {
        const uint32_t so = sb + (uint32_t)(gkt % 3) * STAGE_B;
        #pragma unroll
        for (int ak = 0; ak < 4; ak++) {
            if (ak == 0) {
                if (gkt + 2 < GKT) issue(gkt + 2);
            }
            if (ak < 3) {
                ldfrags((ak + 1) & 1, so, ak + 1);
            } else if (gkt + 1 < GKT) {
                // stage boundary before the last MMA block of this gkt;
                // crosses the tile boundary without draining the pipeline
                if (gkt + 2 < GKT) {
                    asm volatile("cp.async.wait_group 1;" ::: "memory");
                } else {
                    asm volatile("cp.async.wait_group 0;" ::: "memory");
                }
                __syncthreads();
                ldfrags(0, sb + (uint32_t)((gkt + 1) % 3) * STAGE_B, 0);
            }
            const int cur = ak & 1;
            #pragma unroll
            for (int mt = 0; mt < 4; mt++)
                #pragma unroll
                for (int nt = 0; nt < 4; nt++) {
                    const int pp = nt >> 1, ss = (nt & 1) * 2;
                    asm volatile(
                        "mma.sync.aligned.m16n8k8.row.col.f32.tf32.tf32.f32 "
                        "{%0,%1,%2,%3}, {%4,%5,%6,%7}, {%8,%9}, {%0,%1,%2,%3};"
                        : "+f"(acc[mt][nt][0]), "+f"(acc[mt][nt][1]),
                          "+f"(acc[mt][nt][2]), "+f"(acc[mt][nt][3])
                        : "r"(af[cur][mt][0]), "r"(af[cur][mt][1]),
                          "r"(af[cur][mt][2]), "r"(af[cur][mt][3]),
                          "r"(bf[cur][pp][ss]), "r"(bf[cur][pp][ss + 1]));
                }
        }
        if (gkt == 7) {
            // tile 0 finished; its epilogue overlaps tile 1's in-flight cp.asyncs
            epilogue(tn0);
            #pragma unroll
            for (int mt = 0; mt < 4; mt++)
                #pragma unroll
                for (int nt = 0; nt < 4; nt++)
                    #pragma unroll
                    for (int q = 0; q < 4; q++) acc[mt][nt][q] = 0.f;
        }
    }
    epilogue(tn1);
}

// ---------------- launch ----------------
extern "C" void kernel_launch(void* const* d_in, const int* in_sizes, int n_in,
                              void* d_out, int out_size) {
    const float* x = (const float*)d_in[0];   // [8192, 256]
    const float* p = (const float*)d_in[1];   // [8192, 256]
    float* out = (float*)d_out;               // [8192, 8192]

    static bool configured = false;
    if (!configured) {
        cudaFuncSetAttribute(gauss_mma_kernel,
                             cudaFuncAttributeMaxDynamicSharedMemorySize, SMEM_BYTES);
        configured = true;
    }

    prep_kernel<<<NB + NP, 256>>>(x, p);

    gauss_mma_kernel<<<(NB / BM) * (NP / BN) / 2, 256, SMEM_BYTES>>>(out);
}